// round 3
// baseline (speedup 1.0000x reference)
#include <cuda_runtime.h>
#include <cuda_bf16.h>
#include <math.h>

// Problem dims
#define B_  512
#define H_  1024
#define L_  256
#define V_  10000
#define H2_ 2048
#define H3_ 3072

// ---------------- scratch (device globals; no allocation) ----------------
__device__ float g_embedded[B_ * H_];
__device__ float g_comb[B_ * H2_];        // reused for both concats (sequential)
__device__ float g_attn_applied[B_ * H_];
__device__ float g_x[B_ * H_];
__device__ float g_gi[B_ * H3_];
__device__ float g_gh[B_ * H3_];

// ---------------- gather: embedded = emb[input_ids] ----------------
__global__ void gather_kernel(const int* __restrict__ ids,
                              const float* __restrict__ emb) {
    int i = blockIdx.x * blockDim.x + threadIdx.x;   // B*H
    int b = i >> 10;
    int j = i & (H_ - 1);
    g_embedded[i] = emb[(size_t)ids[b] * H_ + j];
}

// ---------------- concat [a | c] -> g_comb (B, 2H) ----------------
__global__ void concat_kernel(const float* __restrict__ a,
                              const float* __restrict__ c) {
    int i = blockIdx.x * blockDim.x + threadIdx.x;   // B*2H
    int b = i >> 11;
    int j = i & (H2_ - 1);
    g_comb[i] = (j < H_) ? a[b * H_ + j] : c[b * H_ + (j - H_)];
}

// ---------------- generic tiled fp32 GEMM: C = A(M,K) * W(K,N) + bias ----------------
// BM=BN=64, BK=16, 256 threads, 4x4 per thread.
template <int RELU>
__global__ void gemm_bias_kernel(const float* __restrict__ A,
                                 const float* __restrict__ W,
                                 const float* __restrict__ bias,
                                 float* __restrict__ C,
                                 int M, int N, int K) {
    __shared__ float As[16][64];
    __shared__ float Ws[16][68];  // +4 pad, keeps 16B alignment for float4 reads
    const int tid = threadIdx.x;
    const int bm = blockIdx.y * 64;
    const int bn = blockIdx.x * 64;
    const int tm = (tid >> 4) * 4;
    const int tn = (tid & 15) * 4;
    float acc[4][4] = {};

    for (int k0 = 0; k0 < K; k0 += 16) {
#pragma unroll
        for (int i = 0; i < 4; i++) {
            int idx = tid + i * 256;
            int m = idx >> 4, k = idx & 15;
            As[k][m] = A[(size_t)(bm + m) * K + (k0 + k)];
        }
#pragma unroll
        for (int i = 0; i < 4; i++) {
            int idx = tid + i * 256;
            int k = idx >> 6, n = idx & 63;
            int gn = bn + n;
            Ws[k][n] = (gn < N) ? W[(size_t)(k0 + k) * N + gn] : 0.f;
        }
        __syncthreads();
#pragma unroll
        for (int k = 0; k < 16; k++) {
            float4 a4 = *reinterpret_cast<const float4*>(&As[k][tm]);
            float4 w4 = *reinterpret_cast<const float4*>(&Ws[k][tn]);
            float a[4] = {a4.x, a4.y, a4.z, a4.w};
            float w[4] = {w4.x, w4.y, w4.z, w4.w};
#pragma unroll
            for (int i = 0; i < 4; i++)
#pragma unroll
                for (int j = 0; j < 4; j++)
                    acc[i][j] += a[i] * w[j];
        }
        __syncthreads();
    }

#pragma unroll
    for (int i = 0; i < 4; i++) {
        int gm = bm + tm + i;
#pragma unroll
        for (int j = 0; j < 4; j++) {
            int gn = bn + tn + j;
            if (gn < N) {
                float v = acc[i][j] + bias[gn];
                if (RELU) v = fmaxf(v, 0.f);
                C[(size_t)gm * N + gn] = v;
            }
        }
    }
}

// ---------------- softmax over L=256, in place, one block per row ----------------
__global__ void softmax256_kernel(float* __restrict__ x) {
    int b = blockIdx.x;
    int t = threadIdx.x;
    float* row = x + b * L_;
    __shared__ float red[256];
    float v = row[t];
    red[t] = v;
    __syncthreads();
    for (int s = 128; s; s >>= 1) {
        if (t < s) red[t] = fmaxf(red[t], red[t + s]);
        __syncthreads();
    }
    float m = red[0];
    __syncthreads();
    float e = expf(v - m);
    red[t] = e;
    __syncthreads();
    for (int s = 128; s; s >>= 1) {
        if (t < s) red[t] += red[t + s];
        __syncthreads();
    }
    row[t] = e / red[0];
}

// ---------------- attn_applied[b,h] = sum_l w[b,l] * enc[b,l,h] ----------------
__global__ void attn_apply_kernel(const float* __restrict__ attw,
                                  const float* __restrict__ enc) {
    int b = blockIdx.x;
    int t = threadIdx.x;  // 256 threads, float4 over H=1024
    __shared__ float w[L_];
    w[t] = attw[b * L_ + t];
    __syncthreads();
    const float4* e = reinterpret_cast<const float4*>(enc + (size_t)b * L_ * H_);
    float4 acc = make_float4(0.f, 0.f, 0.f, 0.f);
#pragma unroll 4
    for (int l = 0; l < L_; l++) {
        float4 v = e[l * (H_ / 4) + t];
        float wl = w[l];
        acc.x += wl * v.x;
        acc.y += wl * v.y;
        acc.z += wl * v.z;
        acc.w += wl * v.w;
    }
    reinterpret_cast<float4*>(g_attn_applied + (size_t)b * H_)[t] = acc;
}

// ---------------- GRU elementwise ----------------
__global__ void gru_kernel(const float* __restrict__ h,
                           float* __restrict__ new_h) {
    int i = blockIdx.x * blockDim.x + threadIdx.x;  // B*H
    int b = i >> 10;
    int j = i & (H_ - 1);
    const float* gib = g_gi + (size_t)b * H3_;
    const float* ghb = g_gh + (size_t)b * H3_;
    float r = 1.f / (1.f + expf(-(gib[j] + ghb[j])));
    float z = 1.f / (1.f + expf(-(gib[H_ + j] + ghb[H_ + j])));
    float n = tanhf(gib[2 * H_ + j] + r * ghb[2 * H_ + j]);
    new_h[i] = (1.f - z) * n + z * h[i];
}

// ---------------- log_softmax over V=10000, in place, one block per row ----------------
__global__ void logsoftmax_kernel(float* __restrict__ x) {
    int b = blockIdx.x;
    int t = threadIdx.x;  // 256
    float* row = x + (size_t)b * V_;
    __shared__ float red[256];
    float m = -1e30f;
    for (int i = t; i < V_; i += 256) m = fmaxf(m, row[i]);
    red[t] = m;
    __syncthreads();
    for (int s = 128; s; s >>= 1) {
        if (t < s) red[t] = fmaxf(red[t], red[t + s]);
        __syncthreads();
    }
    m = red[0];
    __syncthreads();
    float sum = 0.f;
    for (int i = t; i < V_; i += 256) sum += expf(row[i] - m);
    red[t] = sum;
    __syncthreads();
    for (int s = 128; s; s >>= 1) {
        if (t < s) red[t] += red[t + s];
        __syncthreads();
    }
    float lse = m + logf(red[0]);
    for (int i = t; i < V_; i += 256) row[i] -= lse;
}

// ---------------- launch ----------------
extern "C" void kernel_launch(void* const* d_in, const int* in_sizes, int n_in,
                              void* d_out, int out_size) {
    const int*   input_ids = (const int*)d_in[0];
    const float* hidden    = (const float*)d_in[1];
    const float* enc       = (const float*)d_in[2];
    const float* emb       = (const float*)d_in[3];
    const float* attn_w    = (const float*)d_in[4];
    const float* attn_b    = (const float*)d_in[5];
    const float* comb_w    = (const float*)d_in[6];
    const float* comb_b    = (const float*)d_in[7];
    const float* w_ih      = (const float*)d_in[8];
    const float* w_hh      = (const float*)d_in[9];
    const float* b_ih      = (const float*)d_in[10];
    const float* b_hh      = (const float*)d_in[11];
    const float* out_w     = (const float*)d_in[12];
    const float* out_b     = (const float*)d_in[13];

    float* out       = (float*)d_out;                   // (B, V) log-probs
    float* new_h_out = out + (size_t)B_ * V_;           // (B, H)
    float* attw_out  = new_h_out + (size_t)B_ * H_;     // (B, L)

    float *p_emb, *p_comb, *p_app, *p_x, *p_gi, *p_gh;
    cudaGetSymbolAddress((void**)&p_emb,  g_embedded);
    cudaGetSymbolAddress((void**)&p_comb, g_comb);
    cudaGetSymbolAddress((void**)&p_app,  g_attn_applied);
    cudaGetSymbolAddress((void**)&p_x,    g_x);
    cudaGetSymbolAddress((void**)&p_gi,   g_gi);
    cudaGetSymbolAddress((void**)&p_gh,   g_gh);

    // 1. gather
    gather_kernel<<<(B_ * H_) / 256, 256>>>(input_ids, emb);
    // 2. concat [embedded | hidden]
    concat_kernel<<<(B_ * H2_) / 256, 256>>>(p_emb, hidden);
    // 3. attn logits -> attw_out
    {
        dim3 g(L_ / 64, B_ / 64);
        gemm_bias_kernel<0><<<g, 256>>>(p_comb, attn_w, attn_b, attw_out, B_, L_, H2_);
    }
    // 4. softmax over L
    softmax256_kernel<<<B_, 256>>>(attw_out);
    // 5. attn_applied
    attn_apply_kernel<<<B_, 256>>>(attw_out, enc);
    // 6. concat [embedded | attn_applied]
    concat_kernel<<<(B_ * H2_) / 256, 256>>>(p_emb, p_app);
    // 7. x = relu(comb @ comb_w + comb_b)
    {
        dim3 g(H_ / 64, B_ / 64);
        gemm_bias_kernel<1><<<g, 256>>>(p_comb, comb_w, comb_b, p_x, B_, H_, H2_);
    }
    // 8. gi = x @ w_ih + b_ih ; gh = hidden @ w_hh + b_hh
    {
        dim3 g(H3_ / 64, B_ / 64);
        gemm_bias_kernel<0><<<g, 256>>>(p_x, w_ih, b_ih, p_gi, B_, H3_, H_);
        gemm_bias_kernel<0><<<g, 256>>>(hidden, w_hh, b_hh, p_gh, B_, H3_, H_);
    }
    // 9. GRU elementwise -> new_hidden
    gru_kernel<<<(B_ * H_) / 256, 256>>>(hidden, new_h_out);
    // 10. logits = new_hidden @ out_w + out_b
    {
        dim3 g((V_ + 63) / 64, B_ / 64);
        gemm_bias_kernel<0><<<g, 256>>>(new_h_out, out_w, out_b, out, B_, V_, H_);
    }
    // 11. log_softmax rows
    logsoftmax_kernel<<<B_, 256>>>(out);
}

// round 5
// speedup vs baseline: 1.4654x; 1.4654x over previous
#include <cuda_runtime.h>
#include <cuda_bf16.h>
#include <math.h>

// Problem dims
#define B_  512
#define H_  1024
#define L_  256
#define V_  10000
#define H2_ 2048
#define H3_ 3072

// ---------------- scratch (device globals; no allocation) ----------------
__device__ float g_comb[B_ * H2_];        // concat buffer (reused sequentially)
__device__ float g_attn_applied[B_ * H_];
__device__ float g_x[B_ * H_];
__device__ float g_gi[B_ * H3_];
__device__ float g_gh[B_ * H3_];
__device__ float g_part[8 * B_ * L_];     // split-K partials (4MB; also fits 2*B*H)

// ---------------- f32x2 packed FMA helpers ----------------
#define PACK_F32X2(d, lo, hi) \
    asm("mov.b64 %0, {%1, %2};" : "=l"(d) : "f"(lo), "f"(hi))
#define UNPACK_F32X2(lo, hi, v) \
    asm("mov.b64 {%0, %1}, %2;" : "=f"(lo), "=f"(hi) : "l"(v))
#define FMA_F32X2(d, a, b, c) \
    asm("fma.rn.f32x2 %0, %1, %2, %3;" : "=l"(d) : "l"(a), "l"(b), "l"(c))

// ---------------- fused gather+concat: g_comb[b] = [emb[ids[b]] | other[b]] ----------------
__global__ void concat_emb_kernel(const int* __restrict__ ids,
                                  const float* __restrict__ emb,
                                  const float* __restrict__ other) {
    int i = blockIdx.x * blockDim.x + threadIdx.x;   // B*2H
    int b = i >> 11;
    int j = i & (H2_ - 1);
    g_comb[i] = (j < H_) ? emb[(size_t)ids[b] * H_ + j]
                         : other[(size_t)b * H_ + (j - H_)];
}

// ---------------- f32x2 GEMM: C = A(M,K) @ W(K,N) (+bias, +relu) ----------------
// BM=128, BN=64, BK=16, 256 threads, 8x4 per thread as 4 m-pairs x 4 n (FFMA2).
// SPLIT: grid.z K-chunks of kLen each, write partials (no bias) at z*M*N.
template <int RELU, int SPLIT>
__global__ void gemm_f32x2_kernel(const float* __restrict__ A,
                                  const float* __restrict__ W,
                                  const float* __restrict__ bias,
                                  float* __restrict__ C,
                                  int M, int N, int K, int kLen) {
    __shared__ float As[16][128];
    __shared__ float Ws[16][68];   // row stride 68 floats (272B, 16B aligned)

    const int tid = threadIdx.x;
    const int bm = blockIdx.y * 128;
    const int bn = blockIdx.x * 64;
    const int tm = (tid >> 4) * 8;   // 0..120
    const int tn = (tid & 15) * 4;   // 0..60

    // A stage: thread loads 2 float4 along k for row am
    const int am = tid >> 1;             // 0..127
    const int ak = (tid & 1) * 8;        // 0 or 8
    const float* Ap = A + (size_t)(bm + am) * K + ak;
    // W stage: thread loads 1 float4 along n for row wk
    const int wk = tid >> 4;             // 0..15
    const int wn = (tid & 15) * 4;
    const int gnw = bn + wn;
    const float* Wp = W + (size_t)wk * N + gnw;

    unsigned long long acc[4][4];
#pragma unroll
    for (int i = 0; i < 4; i++)
#pragma unroll
        for (int j = 0; j < 4; j++) acc[i][j] = 0ULL;

    const int kbeg = blockIdx.z * kLen;
    const int kend = kbeg + kLen;

    for (int k0 = kbeg; k0 < kend; k0 += 16) {
        float4 av0 = *reinterpret_cast<const float4*>(Ap + k0);
        float4 av1 = *reinterpret_cast<const float4*>(Ap + k0 + 4);
        float4 wv = make_float4(0.f, 0.f, 0.f, 0.f);
        if (gnw < N)
            wv = *reinterpret_cast<const float4*>(Wp + (size_t)k0 * N);

        __syncthreads();   // previous tile fully consumed
        As[ak + 0][am] = av0.x;
        As[ak + 1][am] = av0.y;
        As[ak + 2][am] = av0.z;
        As[ak + 3][am] = av0.w;
        As[ak + 4][am] = av1.x;
        As[ak + 5][am] = av1.y;
        As[ak + 6][am] = av1.z;
        As[ak + 7][am] = av1.w;
        *reinterpret_cast<float4*>(&Ws[wk][wn]) = wv;
        __syncthreads();

#pragma unroll
        for (int k = 0; k < 16; k++) {
            float4 a0 = *reinterpret_cast<const float4*>(&As[k][tm]);
            float4 a1 = *reinterpret_cast<const float4*>(&As[k][tm + 4]);
            float4 w  = *reinterpret_cast<const float4*>(&Ws[k][tn]);
            unsigned long long ap[4], wb[4];
            PACK_F32X2(ap[0], a0.x, a0.y);
            PACK_F32X2(ap[1], a0.z, a0.w);
            PACK_F32X2(ap[2], a1.x, a1.y);
            PACK_F32X2(ap[3], a1.z, a1.w);
            PACK_F32X2(wb[0], w.x, w.x);
            PACK_F32X2(wb[1], w.y, w.y);
            PACK_F32X2(wb[2], w.z, w.z);
            PACK_F32X2(wb[3], w.w, w.w);
#pragma unroll
            for (int i = 0; i < 4; i++)
#pragma unroll
                for (int j = 0; j < 4; j++)
                    FMA_F32X2(acc[i][j], ap[i], wb[j], acc[i][j]);
        }
    }

    float* Cb = SPLIT ? (C + (size_t)blockIdx.z * M * N) : C;
#pragma unroll
    for (int i = 0; i < 4; i++) {
        int r0 = bm + tm + 2 * i;
#pragma unroll
        for (int j = 0; j < 4; j++) {
            int c = bn + tn + j;
            if (c < N) {
                float lo, hi;
                UNPACK_F32X2(lo, hi, acc[i][j]);
                if (!SPLIT) {
                    float bz = bias[c];
                    lo += bz;
                    hi += bz;
                    if (RELU) { lo = fmaxf(lo, 0.f); hi = fmaxf(hi, 0.f); }
                }
                Cb[(size_t)r0 * N + c] = lo;
                Cb[(size_t)(r0 + 1) * N + c] = hi;
            }
        }
    }
}

// ---------------- softmax over L=256: sum 8 K-partials + bias, then softmax ----------------
__global__ void softmax_attn_kernel(const float* __restrict__ attn_b,
                                    float* __restrict__ out) {
    int b = blockIdx.x;
    int t = threadIdx.x;
    float v = attn_b[t];
#pragma unroll
    for (int s = 0; s < 8; s++)
        v += g_part[(size_t)s * B_ * L_ + b * L_ + t];
    __shared__ float red[256];
    red[t] = v;
    __syncthreads();
    for (int s = 128; s; s >>= 1) {
        if (t < s) red[t] = fmaxf(red[t], red[t + s]);
        __syncthreads();
    }
    float m = red[0];
    __syncthreads();
    float e = expf(v - m);
    red[t] = e;
    __syncthreads();
    for (int s = 128; s; s >>= 1) {
        if (t < s) red[t] += red[t + s];
        __syncthreads();
    }
    out[b * L_ + t] = e / red[0];
}

// ---------------- reduce 2 K-partials + bias + relu -> g_x ----------------
__global__ void reduce_relu_kernel(const float* __restrict__ bias) {
    int i = blockIdx.x * blockDim.x + threadIdx.x;   // B*H
    int j = i & (H_ - 1);
    float v = g_part[i] + g_part[B_ * H_ + i] + bias[j];
    g_x[i] = fmaxf(v, 0.f);
}

// ---------------- attn_applied[b,h] = sum_l w[b,l] * enc[b,l,h] ----------------
// grid (H/256, B), 256 threads, one h per thread
__global__ void attn_apply_kernel(const float* __restrict__ attw,
                                  const float* __restrict__ enc) {
    int b = blockIdx.y;
    int hc = blockIdx.x;
    int t = threadIdx.x;
    __shared__ float w[L_];
    w[t] = attw[b * L_ + t];
    __syncthreads();
    int h = hc * 256 + t;
    const float* e = enc + (size_t)b * L_ * H_ + h;
    float acc = 0.f;
#pragma unroll 8
    for (int l = 0; l < L_; l++)
        acc += w[l] * e[(size_t)l * H_];
    g_attn_applied[(size_t)b * H_ + h] = acc;
}

// ---------------- GRU elementwise ----------------
__global__ void gru_kernel(const float* __restrict__ h,
                           float* __restrict__ new_h) {
    int i = blockIdx.x * blockDim.x + threadIdx.x;  // B*H
    int b = i >> 10;
    int j = i & (H_ - 1);
    const float* gib = g_gi + (size_t)b * H3_;
    const float* ghb = g_gh + (size_t)b * H3_;
    float r = 1.f / (1.f + expf(-(gib[j] + ghb[j])));
    float z = 1.f / (1.f + expf(-(gib[H_ + j] + ghb[H_ + j])));
    float n = tanhf(gib[2 * H_ + j] + r * ghb[2 * H_ + j]);
    new_h[i] = (1.f - z) * n + z * h[i];
}

// ---------------- log_softmax over V=10000, in place ----------------
__global__ void logsoftmax_kernel(float* __restrict__ x) {
    int b = blockIdx.x;
    int t = threadIdx.x;  // 256
    float* row = x + (size_t)b * V_;
    __shared__ float red[256];
    float m = -1e30f;
    for (int i = t; i < V_; i += 256) m = fmaxf(m, row[i]);
    red[t] = m;
    __syncthreads();
    for (int s = 128; s; s >>= 1) {
        if (t < s) red[t] = fmaxf(red[t], red[t + s]);
        __syncthreads();
    }
    m = red[0];
    __syncthreads();
    float sum = 0.f;
    for (int i = t; i < V_; i += 256) sum += expf(row[i] - m);
    red[t] = sum;
    __syncthreads();
    for (int s = 128; s; s >>= 1) {
        if (t < s) red[t] += red[t + s];
        __syncthreads();
    }
    float lse = m + logf(red[0]);
    for (int i = t; i < V_; i += 256) row[i] -= lse;
}

// ---------------- launch ----------------
extern "C" void kernel_launch(void* const* d_in, const int* in_sizes, int n_in,
                              void* d_out, int out_size) {
    const int*   input_ids = (const int*)d_in[0];
    const float* hidden    = (const float*)d_in[1];
    const float* enc       = (const float*)d_in[2];
    const float* emb       = (const float*)d_in[3];
    const float* attn_w    = (const float*)d_in[4];
    const float* attn_b    = (const float*)d_in[5];
    const float* comb_w    = (const float*)d_in[6];
    const float* comb_b    = (const float*)d_in[7];
    const float* w_ih      = (const float*)d_in[8];
    const float* w_hh      = (const float*)d_in[9];
    const float* b_ih      = (const float*)d_in[10];
    const float* b_hh      = (const float*)d_in[11];
    const float* out_w     = (const float*)d_in[12];
    const float* out_b     = (const float*)d_in[13];

    float* out       = (float*)d_out;                   // (B, V) log-probs
    float* new_h_out = out + (size_t)B_ * V_;           // (B, H)
    float* attw_out  = new_h_out + (size_t)B_ * H_;     // (B, L)

    float *p_comb, *p_app, *p_x, *p_gi, *p_gh, *p_part;
    cudaGetSymbolAddress((void**)&p_comb, g_comb);
    cudaGetSymbolAddress((void**)&p_app,  g_attn_applied);
    cudaGetSymbolAddress((void**)&p_x,    g_x);
    cudaGetSymbolAddress((void**)&p_gi,   g_gi);
    cudaGetSymbolAddress((void**)&p_gh,   g_gh);
    cudaGetSymbolAddress((void**)&p_part, g_part);

    // 1. g_comb = [emb[ids] | hidden]
    concat_emb_kernel<<<(B_ * H2_) / 256, 256>>>(input_ids, emb, hidden);
    // 2. attn logits, split-K=8 -> partials
    {
        dim3 g(L_ / 64, B_ / 128, 8);
        gemm_f32x2_kernel<0, 1><<<g, 256>>>(p_comb, attn_w, nullptr, p_part,
                                            B_, L_, H2_, H2_ / 8);
    }
    // 3. reduce partials + bias + softmax -> attw_out
    softmax_attn_kernel<<<B_, 256>>>(attn_b, attw_out);
    // 4. attn_applied
    {
        dim3 g(H_ / 256, B_);
        attn_apply_kernel<<<g, 256>>>(attw_out, enc);
    }
    // 5. g_comb = [emb[ids] | attn_applied]
    concat_emb_kernel<<<(B_ * H2_) / 256, 256>>>(input_ids, emb, p_app);
    // 6. comb GEMM, split-K=2 -> partials
    {
        dim3 g(H_ / 64, B_ / 128, 2);
        gemm_f32x2_kernel<0, 1><<<g, 256>>>(p_comb, comb_w, nullptr, p_part,
                                            B_, H_, H2_, H2_ / 2);
    }
    // 7. x = relu(p0 + p1 + bias)
    reduce_relu_kernel<<<(B_ * H_) / 256, 256>>>(comb_b);
    // 8. gi = x @ w_ih + b_ih ; gh = hidden @ w_hh + b_hh
    {
        dim3 g(H3_ / 64, B_ / 128, 1);
        gemm_f32x2_kernel<0, 0><<<g, 256>>>(p_x, w_ih, b_ih, p_gi,
                                            B_, H3_, H_, H_);
        gemm_f32x2_kernel<0, 0><<<g, 256>>>(hidden, w_hh, b_hh, p_gh,
                                            B_, H3_, H_, H_);
    }
    // 9. GRU elementwise -> new_hidden (output slot)
    gru_kernel<<<(B_ * H_) / 256, 256>>>(hidden, new_h_out);
    // 10. logits = new_hidden @ out_w + out_b
    {
        dim3 g((V_ + 63) / 64, B_ / 128, 1);
        gemm_f32x2_kernel<0, 0><<<g, 256>>>(new_h_out, out_w, out_b, out,
                                            B_, V_, H_, H_);
    }
    // 11. log_softmax rows
    logsoftmax_kernel<<<B_, 256>>>(out);
}

// round 7
// speedup vs baseline: 2.6561x; 1.8126x over previous
#include <cuda_runtime.h>
#include <cuda_bf16.h>
#include <math.h>
#include <stdint.h>

// Problem dims
#define B_  512
#define H_  1024
#define L_  256
#define V_  10000
#define H2_ 2048
#define H3_ 3072

// ---------------- scratch (device globals; no allocation) ----------------
__device__ float g_comb[B_ * H2_];        // concat buffer (reused sequentially)
__device__ float g_attn_applied[B_ * H_];
__device__ float g_x[B_ * H_];
__device__ float g_gi[B_ * H3_];
__device__ float g_gh[B_ * H3_];
__device__ float g_part[8 * B_ * L_];     // split-K partials (4MB; also fits 2*B*H)

// ---------------- f32x2 packed FMA helpers (attn GEMM stays exact fp32) ----------------
#define PACK_F32X2(d, lo, hi) \
    asm("mov.b64 %0, {%1, %2};" : "=l"(d) : "f"(lo), "f"(hi))
#define UNPACK_F32X2(lo, hi, v) \
    asm("mov.b64 {%0, %1}, %2;" : "=f"(lo), "=f"(hi) : "l"(v))
#define FMA_F32X2(d, a, b, c) \
    asm("fma.rn.f32x2 %0, %1, %2, %3;" : "=l"(d) : "l"(a), "l"(b), "l"(c))

__device__ __forceinline__ uint32_t f2tf32(float f) {
    uint32_t u;
    asm("cvt.rna.tf32.f32 %0, %1;" : "=r"(u) : "f"(f));
    return u;
}

// ---------------- fused gather+concat: g_comb[b] = [emb[ids[b]] | other[b]] ----------------
__global__ void concat_emb_kernel(const int* __restrict__ ids,
                                  const float* __restrict__ emb,
                                  const float* __restrict__ other) {
    int i = blockIdx.x * blockDim.x + threadIdx.x;   // B*2H
    int b = i >> 11;
    int j = i & (H2_ - 1);
    g_comb[i] = (j < H_) ? emb[(size_t)ids[b] * H_ + j]
                         : other[(size_t)b * H_ + (j - H_)];
}

// ==================== tf32 tensor-core GEMM ====================
// C = A(M,K) @ W(K,N). Block 256 thr = 8 warps; BM=128 BN=64 BK=32.
// Warp grid 4x2 (m x n), warp tile 32x32 = 2x4 m16n8k8 fragments.
// SPLIT: grid.z chunks of kLen, write raw partials at z*M*N (no bias).
struct GemmArgs {
    const float* A;
    const float* W;
    const float* bias;
    float* C;
};

template <int SPLIT>
__device__ __forceinline__ void gemm_tf32_body(const float* __restrict__ A,
                                               const float* __restrict__ W,
                                               const float* __restrict__ bias,
                                               float* __restrict__ C,
                                               int M, int N, int K, int kLen,
                                               int zIdx) {
    __shared__ uint32_t As[128][36];   // [m][k] pad->4*gid+tig distinct banks
    __shared__ uint32_t Ws[32][72];    // [k][n] pad->8*tig+gid distinct banks

    const int tid = threadIdx.x;
    const int lane = tid & 31;
    const int wid = tid >> 5;
    const int gid = lane >> 2;     // 0..7
    const int tig = lane & 3;      // 0..3
    const int warp_m = (wid & 3) * 32;
    const int warp_n = (wid >> 2) * 32;

    const int bm = blockIdx.y * 128;
    const int bn = blockIdx.x * 64;

    // A staging: thread covers rows (tid>>3)+32r, cols (tid&7)*4..+3
    const int sa_r = tid >> 3;         // 0..31
    const int sa_c = (tid & 7) * 4;    // 0..28
    // W staging: rows (tid>>4)+16r, cols (tid&15)*4
    const int sw_r = tid >> 4;         // 0..15
    const int sw_c = (tid & 15) * 4;
    const int gnw = bn + sw_c;
    const bool wok = (gnw < N);        // N multiple of 16 -> whole float4 in/out

    float acc[2][4][4];
#pragma unroll
    for (int mi = 0; mi < 2; mi++)
#pragma unroll
        for (int ni = 0; ni < 4; ni++)
#pragma unroll
            for (int r = 0; r < 4; r++) acc[mi][ni][r] = 0.f;

    const int kbeg = zIdx * kLen;
    const int kend = kbeg + kLen;

    for (int k0 = kbeg; k0 < kend; k0 += 32) {
        // ---- load tiles to registers ----
        float4 av[4];
#pragma unroll
        for (int r = 0; r < 4; r++)
            av[r] = *reinterpret_cast<const float4*>(
                A + (size_t)(bm + sa_r + 32 * r) * K + k0 + sa_c);
        float4 wv[2];
#pragma unroll
        for (int r = 0; r < 2; r++)
            wv[r] = wok ? *reinterpret_cast<const float4*>(
                              W + (size_t)(k0 + sw_r + 16 * r) * N + gnw)
                        : make_float4(0.f, 0.f, 0.f, 0.f);

        __syncthreads();   // previous tile fully consumed
#pragma unroll
        for (int r = 0; r < 4; r++) {
            int m = sa_r + 32 * r;
            As[m][sa_c + 0] = f2tf32(av[r].x);
            As[m][sa_c + 1] = f2tf32(av[r].y);
            As[m][sa_c + 2] = f2tf32(av[r].z);
            As[m][sa_c + 3] = f2tf32(av[r].w);
        }
#pragma unroll
        for (int r = 0; r < 2; r++) {
            int k = sw_r + 16 * r;
            Ws[k][sw_c + 0] = f2tf32(wv[r].x);
            Ws[k][sw_c + 1] = f2tf32(wv[r].y);
            Ws[k][sw_c + 2] = f2tf32(wv[r].z);
            Ws[k][sw_c + 3] = f2tf32(wv[r].w);
        }
        __syncthreads();

        // ---- 4 k-steps of 8 ----
#pragma unroll
        for (int ks = 0; ks < 4; ks++) {
            const int kk = ks * 8;
            uint32_t af[2][4];
#pragma unroll
            for (int mi = 0; mi < 2; mi++) {
                int ar = warp_m + mi * 16 + gid;
                af[mi][0] = As[ar][kk + tig];
                af[mi][1] = As[ar + 8][kk + tig];
                af[mi][2] = As[ar][kk + tig + 4];
                af[mi][3] = As[ar + 8][kk + tig + 4];
            }
            uint32_t bf[4][2];
#pragma unroll
            for (int ni = 0; ni < 4; ni++) {
                int bc = warp_n + ni * 8 + gid;
                bf[ni][0] = Ws[kk + tig][bc];
                bf[ni][1] = Ws[kk + tig + 4][bc];
            }
#pragma unroll
            for (int mi = 0; mi < 2; mi++)
#pragma unroll
                for (int ni = 0; ni < 4; ni++) {
                    asm volatile(
                        "mma.sync.aligned.m16n8k8.row.col.f32.tf32.tf32.f32 "
                        "{%0,%1,%2,%3}, {%4,%5,%6,%7}, {%8,%9}, {%0,%1,%2,%3};\n"
                        : "+f"(acc[mi][ni][0]), "+f"(acc[mi][ni][1]),
                          "+f"(acc[mi][ni][2]), "+f"(acc[mi][ni][3])
                        : "r"(af[mi][0]), "r"(af[mi][1]),
                          "r"(af[mi][2]), "r"(af[mi][3]),
                          "r"(bf[ni][0]), "r"(bf[ni][1]));
                }
        }
    }

    // ---- epilogue ----
    float* Cb = SPLIT ? (C + (size_t)zIdx * M * N) : C;
#pragma unroll
    for (int mi = 0; mi < 2; mi++) {
        int r0 = bm + warp_m + mi * 16 + gid;
#pragma unroll
        for (int ni = 0; ni < 4; ni++) {
            int c0 = bn + warp_n + ni * 8 + 2 * tig;
            if (c0 < N) {
                float v0 = acc[mi][ni][0], v1 = acc[mi][ni][1];
                float v2 = acc[mi][ni][2], v3 = acc[mi][ni][3];
                if (!SPLIT) {
                    float bz0 = bias[c0];
                    float bz1 = (c0 + 1 < N) ? bias[c0 + 1] : 0.f;
                    v0 += bz0; v1 += bz1; v2 += bz0; v3 += bz1;
                }
                Cb[(size_t)r0 * N + c0] = v0;
                Cb[(size_t)(r0 + 8) * N + c0] = v2;
                if (c0 + 1 < N) {
                    Cb[(size_t)r0 * N + c0 + 1] = v1;
                    Cb[(size_t)(r0 + 8) * N + c0 + 1] = v3;
                }
            }
        }
    }
}

template <int SPLIT>
__global__ void gemm_tf32_kernel(const float* __restrict__ A,
                                 const float* __restrict__ W,
                                 const float* __restrict__ bias,
                                 float* __restrict__ C,
                                 int M, int N, int K, int kLen) {
    gemm_tf32_body<SPLIT>(A, W, bias, C, M, N, K, kLen, blockIdx.z);
}

// dual: z selects (A0,W0,b0,C0) vs (A1,W1,b1,C1); full-K each
__global__ void gemm_tf32_dual_kernel(GemmArgs g0, GemmArgs g1,
                                      int M, int N, int K) {
    if (blockIdx.z == 0)
        gemm_tf32_body<0>(g0.A, g0.W, g0.bias, g0.C, M, N, K, K, 0);
    else
        gemm_tf32_body<0>(g1.A, g1.W, g1.bias, g1.C, M, N, K, K, 0);
}

// ---------------- exact-fp32 FFMA2 GEMM (attn logits only) ----------------
// BM=128, BN=64, BK=16, 256 threads, 8x4 per thread, split-K partials.
__global__ void gemm_f32x2_split_kernel(const float* __restrict__ A,
                                        const float* __restrict__ W,
                                        float* __restrict__ C,
                                        int M, int N, int K, int kLen) {
    __shared__ float As[16][128];
    __shared__ float Ws[16][68];

    const int tid = threadIdx.x;
    const int bm = blockIdx.y * 128;
    const int bn = blockIdx.x * 64;
    const int tm = (tid >> 4) * 8;
    const int tn = (tid & 15) * 4;

    const int am = tid >> 1;
    const int ak = (tid & 1) * 8;
    const float* Ap = A + (size_t)(bm + am) * K + ak;
    const int wk = tid >> 4;
    const int wn = (tid & 15) * 4;
    const int gnw = bn + wn;
    const float* Wp = W + (size_t)wk * N + gnw;

    unsigned long long acc[4][4];
#pragma unroll
    for (int i = 0; i < 4; i++)
#pragma unroll
        for (int j = 0; j < 4; j++) acc[i][j] = 0ULL;

    const int kbeg = blockIdx.z * kLen;
    const int kend = kbeg + kLen;

    for (int k0 = kbeg; k0 < kend; k0 += 16) {
        float4 av0 = *reinterpret_cast<const float4*>(Ap + k0);
        float4 av1 = *reinterpret_cast<const float4*>(Ap + k0 + 4);
        float4 wv = make_float4(0.f, 0.f, 0.f, 0.f);
        if (gnw < N)
            wv = *reinterpret_cast<const float4*>(Wp + (size_t)k0 * N);

        __syncthreads();
        As[ak + 0][am] = av0.x; As[ak + 1][am] = av0.y;
        As[ak + 2][am] = av0.z; As[ak + 3][am] = av0.w;
        As[ak + 4][am] = av1.x; As[ak + 5][am] = av1.y;
        As[ak + 6][am] = av1.z; As[ak + 7][am] = av1.w;
        *reinterpret_cast<float4*>(&Ws[wk][wn]) = wv;
        __syncthreads();

#pragma unroll
        for (int k = 0; k < 16; k++) {
            float4 a0 = *reinterpret_cast<const float4*>(&As[k][tm]);
            float4 a1 = *reinterpret_cast<const float4*>(&As[k][tm + 4]);
            float4 w  = *reinterpret_cast<const float4*>(&Ws[k][tn]);
            unsigned long long ap[4], wb[4];
            PACK_F32X2(ap[0], a0.x, a0.y);
            PACK_F32X2(ap[1], a0.z, a0.w);
            PACK_F32X2(ap[2], a1.x, a1.y);
            PACK_F32X2(ap[3], a1.z, a1.w);
            PACK_F32X2(wb[0], w.x, w.x);
            PACK_F32X2(wb[1], w.y, w.y);
            PACK_F32X2(wb[2], w.z, w.z);
            PACK_F32X2(wb[3], w.w, w.w);
#pragma unroll
            for (int i = 0; i < 4; i++)
#pragma unroll
                for (int j = 0; j < 4; j++)
                    FMA_F32X2(acc[i][j], ap[i], wb[j], acc[i][j]);
        }
    }

    float* Cb = C + (size_t)blockIdx.z * M * N;
#pragma unroll
    for (int i = 0; i < 4; i++) {
        int r0 = bm + tm + 2 * i;
#pragma unroll
        for (int j = 0; j < 4; j++) {
            int c = bn + tn + j;
            if (c < N) {
                float lo, hi;
                UNPACK_F32X2(lo, hi, acc[i][j]);
                Cb[(size_t)r0 * N + c] = lo;
                Cb[(size_t)(r0 + 1) * N + c] = hi;
            }
        }
    }
}

// ---------------- softmax over L=256: sum 8 K-partials + bias, then softmax ----------------
__global__ void softmax_attn_kernel(const float* __restrict__ attn_b,
                                    float* __restrict__ out) {
    int b = blockIdx.x;
    int t = threadIdx.x;
    float v = attn_b[t];
#pragma unroll
    for (int s = 0; s < 8; s++)
        v += g_part[(size_t)s * B_ * L_ + b * L_ + t];
    __shared__ float red[256];
    red[t] = v;
    __syncthreads();
    for (int s = 128; s; s >>= 1) {
        if (t < s) red[t] = fmaxf(red[t], red[t + s]);
        __syncthreads();
    }
    float m = red[0];
    __syncthreads();
    float e = expf(v - m);
    red[t] = e;
    __syncthreads();
    for (int s = 128; s; s >>= 1) {
        if (t < s) red[t] += red[t + s];
        __syncthreads();
    }
    out[b * L_ + t] = e / red[0];
}

// ---------------- reduce 2 K-partials + bias + relu -> g_x ----------------
__global__ void reduce_relu_kernel(const float* __restrict__ bias) {
    int i = blockIdx.x * blockDim.x + threadIdx.x;   // B*H
    int j = i & (H_ - 1);
    float v = g_part[i] + g_part[B_ * H_ + i] + bias[j];
    g_x[i] = fmaxf(v, 0.f);
}

// ---------------- attn_applied[b,h] = sum_l w[b,l] * enc[b,l,h] ----------------
__global__ void attn_apply_kernel(const float* __restrict__ attw,
                                  const float* __restrict__ enc) {
    int b = blockIdx.y;
    int hc = blockIdx.x;
    int t = threadIdx.x;
    __shared__ float w[L_];
    w[t] = attw[b * L_ + t];
    __syncthreads();
    int h = hc * 256 + t;
    const float* e = enc + (size_t)b * L_ * H_ + h;
    float acc = 0.f;
#pragma unroll 8
    for (int l = 0; l < L_; l++)
        acc += w[l] * e[(size_t)l * H_];
    g_attn_applied[(size_t)b * H_ + h] = acc;
}

// ---------------- GRU elementwise ----------------
__global__ void gru_kernel(const float* __restrict__ h,
                           float* __restrict__ new_h) {
    int i = blockIdx.x * blockDim.x + threadIdx.x;  // B*H
    int b = i >> 10;
    int j = i & (H_ - 1);
    const float* gib = g_gi + (size_t)b * H3_;
    const float* ghb = g_gh + (size_t)b * H3_;
    float r = 1.f / (1.f + expf(-(gib[j] + ghb[j])));
    float z = 1.f / (1.f + expf(-(gib[H_ + j] + ghb[H_ + j])));
    float n = tanhf(gib[2 * H_ + j] + r * ghb[2 * H_ + j]);
    new_h[i] = (1.f - z) * n + z * h[i];
}

// ---------------- log_softmax over V=10000, in place ----------------
__global__ void logsoftmax_kernel(float* __restrict__ x) {
    int b = blockIdx.x;
    int t = threadIdx.x;  // 256
    float* row = x + (size_t)b * V_;
    __shared__ float red[256];
    float m = -1e30f;
    for (int i = t; i < V_; i += 256) m = fmaxf(m, row[i]);
    red[t] = m;
    __syncthreads();
    for (int s = 128; s; s >>= 1) {
        if (t < s) red[t] = fmaxf(red[t], red[t + s]);
        __syncthreads();
    }
    m = red[0];
    __syncthreads();
    float sum = 0.f;
    for (int i = t; i < V_; i += 256) sum += expf(row[i] - m);
    red[t] = sum;
    __syncthreads();
    for (int s = 128; s; s >>= 1) {
        if (t < s) red[t] += red[t + s];
        __syncthreads();
    }
    float lse = m + logf(red[0]);
    for (int i = t; i < V_; i += 256) row[i] -= lse;
}

// ---------------- launch ----------------
extern "C" void kernel_launch(void* const* d_in, const int* in_sizes, int n_in,
                              void* d_out, int out_size) {
    const int*   input_ids = (const int*)d_in[0];
    const float* hidden    = (const float*)d_in[1];
    const float* enc       = (const float*)d_in[2];
    const float* emb       = (const float*)d_in[3];
    const float* attn_w    = (const float*)d_in[4];
    const float* attn_b    = (const float*)d_in[5];
    const float* comb_w    = (const float*)d_in[6];
    const float* comb_b    = (const float*)d_in[7];
    const float* w_ih      = (const float*)d_in[8];
    const float* w_hh      = (const float*)d_in[9];
    const float* b_ih      = (const float*)d_in[10];
    const float* b_hh      = (const float*)d_in[11];
    const float* out_w     = (const float*)d_in[12];
    const float* out_b     = (const float*)d_in[13];

    float* out       = (float*)d_out;                   // (B, V) log-probs
    float* new_h_out = out + (size_t)B_ * V_;           // (B, H)
    float* attw_out  = new_h_out + (size_t)B_ * H_;     // (B, L)

    float *p_comb, *p_app, *p_x, *p_gi, *p_gh, *p_part;
    cudaGetSymbolAddress((void**)&p_comb, g_comb);
    cudaGetSymbolAddress((void**)&p_app,  g_attn_applied);
    cudaGetSymbolAddress((void**)&p_x,    g_x);
    cudaGetSymbolAddress((void**)&p_gi,   g_gi);
    cudaGetSymbolAddress((void**)&p_gh,   g_gh);
    cudaGetSymbolAddress((void**)&p_part, g_part);

    // 1. g_comb = [emb[ids] | hidden]
    concat_emb_kernel<<<(B_ * H2_) / 256, 256>>>(input_ids, emb, hidden);
    // 2. attn logits, exact fp32, split-K=8 -> partials
    {
        dim3 g(L_ / 64, B_ / 128, 8);
        gemm_f32x2_split_kernel<<<g, 256>>>(p_comb, attn_w, p_part,
                                            B_, L_, H2_, H2_ / 8);
    }
    // 3. reduce partials + bias + softmax -> attw_out
    softmax_attn_kernel<<<B_, 256>>>(attn_b, attw_out);
    // 4. attn_applied
    {
        dim3 g(H_ / 256, B_);
        attn_apply_kernel<<<g, 256>>>(attw_out, enc);
    }
    // 5. g_comb = [emb[ids] | attn_applied]
    concat_emb_kernel<<<(B_ * H2_) / 256, 256>>>(input_ids, emb, p_app);
    // 6. comb GEMM (tf32), split-K=2 -> partials
    {
        dim3 g(H_ / 64, B_ / 128, 2);
        gemm_tf32_kernel<1><<<g, 256>>>(p_comb, comb_w, nullptr, p_part,
                                        B_, H_, H2_, H2_ / 2);
    }
    // 7. x = relu(p0 + p1 + bias)
    reduce_relu_kernel<<<(B_ * H_) / 256, 256>>>(comb_b);
    // 8. gi = x @ w_ih + b_ih ; gh = hidden @ w_hh + b_hh  (one dual launch)
    {
        dim3 g(H3_ / 64, B_ / 128, 2);
        GemmArgs g0 = {p_x,    w_ih, b_ih, p_gi};
        GemmArgs g1 = {hidden, w_hh, b_hh, p_gh};
        gemm_tf32_dual_kernel<<<g, 256>>>(g0, g1, B_, H3_, H_);
    }
    // 9. GRU elementwise -> new_hidden (output slot)
    gru_kernel<<<(B_ * H_) / 256, 256>>>(hidden, new_h_out);
    // 10. logits = new_hidden @ out_w + out_b (tf32)
    {
        dim3 g((V_ + 63) / 64, B_ / 128, 1);
        gemm_tf32_kernel<0><<<g, 256>>>(new_h_out, out_w, out_b, out,
                                        B_, V_, H_, H_);
    }
    // 11. log_softmax rows
    logsoftmax_kernel<<<B_, 256>>>(out);
}

// round 10
// speedup vs baseline: 2.8342x; 1.0671x over previous
#include <cuda_runtime.h>
#include <cuda_bf16.h>
#include <math.h>
#include <stdint.h>

// Problem dims
#define B_  512
#define H_  1024
#define L_  256
#define V_  10000
#define H2_ 2048
#define H3_ 3072

// ---------------- scratch (device globals; no allocation) ----------------
__device__ float g_comb[B_ * H2_];
__device__ float g_attn_applied[B_ * H_];
__device__ float g_x[B_ * H_];
__device__ float g_gi[B_ * H3_];
__device__ float g_gh[B_ * H3_];
__device__ float g_part[8 * B_ * L_];

// ---------------- helpers ----------------
#define PACK_F32X2(d, lo, hi) \
    asm("mov.b64 %0, {%1, %2};" : "=l"(d) : "f"(lo), "f"(hi))
#define UNPACK_F32X2(lo, hi, v) \
    asm("mov.b64 {%0, %1}, %2;" : "=f"(lo), "=f"(hi) : "l"(v))
#define FMA_F32X2(d, a, b, c) \
    asm("fma.rn.f32x2 %0, %1, %2, %3;" : "=l"(d) : "l"(a), "l"(b), "l"(c))

__device__ __forceinline__ uint32_t f2tf32(float f) {
    uint32_t u;
    asm("cvt.rna.tf32.f32 %0, %1;" : "=r"(u) : "f"(f));
    return u;
}

// ---------------- fused gather+concat ----------------
__global__ void concat_emb_kernel(const int* __restrict__ ids,
                                  const float* __restrict__ emb,
                                  const float* __restrict__ other) {
    int i = blockIdx.x * blockDim.x + threadIdx.x;
    int b = i >> 11;
    int j = i & (H2_ - 1);
    g_comb[i] = (j < H_) ? emb[(size_t)ids[b] * H_ + j]
                         : other[(size_t)b * H_ + (j - H_)];
}

// ==================== pipelined legacy tf32 mma GEMM ====================
// C = A(M,K) @ W(K,N) (+bias). 256 thr = 8 warps (4m x 2n), BM=128 BN=64 BK=32.
// Double-buffered DYNAMIC smem, one __syncthreads per k-tile, STS.128 staging.
// As stride 36 u32 (frag banks 4*gid+tig), Ws stride 68 u32 (banks 4*tig+gid).
struct GemmArgs {
    const float* A;
    const float* W;
    const float* bias;
    float* C;
};

// dynamic smem layout (u32 units):
//   As: [2][128][36]  -> 9216 u32
//   Ws: [2][32][68]   -> 4352 u32
// total 13568 u32 = 54272 bytes
#define GSM_AS_STRIDE 36
#define GSM_WS_STRIDE 68
#define GSM_AS_BUF    (128 * GSM_AS_STRIDE)     // 4608
#define GSM_WS_BUF    (32 * GSM_WS_STRIDE)      // 2176
#define GSM_WS_BASE   (2 * GSM_AS_BUF)          // 9216
#define GSM_BYTES     ((2 * GSM_AS_BUF + 2 * GSM_WS_BUF) * 4)  // 54272

template <bool ADDBIAS>
__device__ __forceinline__ void gemm_core(const float* __restrict__ A,
                                          const float* __restrict__ W,
                                          const float* __restrict__ bias,
                                          float* __restrict__ C,
                                          int N, int K, int kbeg, int kT) {
    extern __shared__ uint32_t dsm[];
    uint32_t* As_ = dsm;                 // [2][128][36]
    uint32_t* Ws_ = dsm + GSM_WS_BASE;   // [2][32][68]

#define AS(p, m, k) As_[(p) * GSM_AS_BUF + (m) * GSM_AS_STRIDE + (k)]
#define WS(p, k, n) Ws_[(p) * GSM_WS_BUF + (k) * GSM_WS_STRIDE + (n)]

    const int tid = threadIdx.x;
    const int lane = tid & 31;
    const int wid = tid >> 5;
    const int gid = lane >> 2;
    const int tig = lane & 3;
    const int warp_m = (wid & 3) * 32;
    const int warp_n = (wid >> 2) * 32;

    const int bm = blockIdx.y * 128;
    const int bn = blockIdx.x * 64;

    // staging assignment
    const int sa_r = tid >> 3;          // 0..31 (+32r)
    const int sa_c = (tid & 7) * 4;     // 0..28
    const int sw_r = tid >> 4;          // 0..15 (+16r)
    const int sw_c = (tid & 15) * 4;    // 0..60
    const int gnw = bn + sw_c;
    const bool wok = (gnw < N);

    const float* Ap = A + (size_t)(bm + sa_r) * K + kbeg + sa_c;
    const float* Wp = W + (size_t)(kbeg + sw_r) * N + gnw;

    float acc[2][4][4];
#pragma unroll
    for (int mi = 0; mi < 2; mi++)
#pragma unroll
        for (int ni = 0; ni < 4; ni++)
#pragma unroll
            for (int r = 0; r < 4; r++) acc[mi][ni][r] = 0.f;

    float4 av[4];
    float4 wv[2];

    auto LDG = [&](int t) {
        const float* ap = Ap + t * 32;
#pragma unroll
        for (int r = 0; r < 4; r++)
            av[r] = *reinterpret_cast<const float4*>(ap + (size_t)(32 * r) * K);
        const float* wp = Wp + (size_t)(t * 32) * N;
#pragma unroll
        for (int r = 0; r < 2; r++)
            wv[r] = wok ? *reinterpret_cast<const float4*>(wp + (size_t)(16 * r) * N)
                        : make_float4(0.f, 0.f, 0.f, 0.f);
    };

    auto STS = [&](int p) {
#pragma unroll
        for (int r = 0; r < 4; r++) {
            int m = sa_r + 32 * r;
            uint4 t4;
            t4.x = f2tf32(av[r].x);
            t4.y = f2tf32(av[r].y);
            t4.z = f2tf32(av[r].z);
            t4.w = f2tf32(av[r].w);
            *reinterpret_cast<uint4*>(&AS(p, m, sa_c)) = t4;
        }
#pragma unroll
        for (int r = 0; r < 2; r++) {
            int k = sw_r + 16 * r;
            uint4 t4;
            t4.x = f2tf32(wv[r].x);
            t4.y = f2tf32(wv[r].y);
            t4.z = f2tf32(wv[r].z);
            t4.w = f2tf32(wv[r].w);
            *reinterpret_cast<uint4*>(&WS(p, k, sw_c)) = t4;
        }
    };

    LDG(0);
    STS(0);
    __syncthreads();

    int p = 0;
    for (int t = 0; t < kT; t++) {
        if (t + 1 < kT) LDG(t + 1);

#pragma unroll
        for (int ks = 0; ks < 4; ks++) {
            const int kk = ks * 8;
            uint32_t af[2][4];
#pragma unroll
            for (int mi = 0; mi < 2; mi++) {
                int ar = warp_m + mi * 16 + gid;
                af[mi][0] = AS(p, ar, kk + tig);
                af[mi][1] = AS(p, ar + 8, kk + tig);
                af[mi][2] = AS(p, ar, kk + tig + 4);
                af[mi][3] = AS(p, ar + 8, kk + tig + 4);
            }
            uint32_t bf[4][2];
#pragma unroll
            for (int ni = 0; ni < 4; ni++) {
                int bc = warp_n + ni * 8 + gid;
                bf[ni][0] = WS(p, kk + tig, bc);
                bf[ni][1] = WS(p, kk + tig + 4, bc);
            }
#pragma unroll
            for (int mi = 0; mi < 2; mi++)
#pragma unroll
                for (int ni = 0; ni < 4; ni++) {
                    asm volatile(
                        "mma.sync.aligned.m16n8k8.row.col.f32.tf32.tf32.f32 "
                        "{%0,%1,%2,%3}, {%4,%5,%6,%7}, {%8,%9}, {%0,%1,%2,%3};\n"
                        : "+f"(acc[mi][ni][0]), "+f"(acc[mi][ni][1]),
                          "+f"(acc[mi][ni][2]), "+f"(acc[mi][ni][3])
                        : "r"(af[mi][0]), "r"(af[mi][1]),
                          "r"(af[mi][2]), "r"(af[mi][3]),
                          "r"(bf[ni][0]), "r"(bf[ni][1]));
                }
        }

        if (t + 1 < kT) STS(p ^ 1);
        __syncthreads();
        p ^= 1;
    }

    // epilogue
#pragma unroll
    for (int mi = 0; mi < 2; mi++) {
        int r0 = bm + warp_m + mi * 16 + gid;
#pragma unroll
        for (int ni = 0; ni < 4; ni++) {
            int c0 = bn + warp_n + ni * 8 + 2 * tig;
            if (c0 < N) {
                float v0 = acc[mi][ni][0], v1 = acc[mi][ni][1];
                float v2 = acc[mi][ni][2], v3 = acc[mi][ni][3];
                if (ADDBIAS) {
                    float bz0 = bias[c0];
                    float bz1 = (c0 + 1 < N) ? bias[c0 + 1] : 0.f;
                    v0 += bz0; v1 += bz1; v2 += bz0; v3 += bz1;
                }
                C[(size_t)r0 * N + c0] = v0;
                C[(size_t)(r0 + 8) * N + c0] = v2;
                if (c0 + 1 < N) {
                    C[(size_t)r0 * N + c0 + 1] = v1;
                    C[(size_t)(r0 + 8) * N + c0 + 1] = v3;
                }
            }
        }
    }
#undef AS
#undef WS
}

// MODE: 0 = plain (full K, bias), 1 = split-K (z = k-chunk, raw partials),
//       2 = dual (z selects arg set, full K, bias)
template <int MODE>
__global__ void __launch_bounds__(256)
gemm_tf32p(GemmArgs g0, GemmArgs g1, int M, int N, int K, int kLen) {
    const GemmArgs ga = (MODE == 2 && blockIdx.z == 1) ? g1 : g0;
    const int kbeg = (MODE == 1) ? blockIdx.z * kLen : 0;
    const int kT = ((MODE == 1) ? kLen : K) / 32;
    float* C = ga.C + ((MODE == 1) ? (size_t)blockIdx.z * M * N : 0);
    if (MODE == 1)
        gemm_core<false>(ga.A, ga.W, ga.bias, C, N, K, kbeg, kT);
    else
        gemm_core<true>(ga.A, ga.W, ga.bias, C, N, K, kbeg, kT);
}

// ---------------- exact-fp32 FFMA2 GEMM (attn logits only) ----------------
__global__ void gemm_f32x2_split_kernel(const float* __restrict__ A,
                                        const float* __restrict__ W,
                                        float* __restrict__ C,
                                        int M, int N, int K, int kLen) {
    __shared__ float As[16][128];
    __shared__ float Ws[16][68];

    const int tid = threadIdx.x;
    const int bm = blockIdx.y * 128;
    const int bn = blockIdx.x * 64;
    const int tm = (tid >> 4) * 8;
    const int tn = (tid & 15) * 4;

    const int am = tid >> 1;
    const int ak = (tid & 1) * 8;
    const float* Ap = A + (size_t)(bm + am) * K + ak;
    const int wk = tid >> 4;
    const int wn = (tid & 15) * 4;
    const int gnw = bn + wn;
    const float* Wp = W + (size_t)wk * N + gnw;

    unsigned long long acc[4][4];
#pragma unroll
    for (int i = 0; i < 4; i++)
#pragma unroll
        for (int j = 0; j < 4; j++) acc[i][j] = 0ULL;

    const int kbeg = blockIdx.z * kLen;
    const int kend = kbeg + kLen;

    for (int k0 = kbeg; k0 < kend; k0 += 16) {
        float4 av0 = *reinterpret_cast<const float4*>(Ap + k0);
        float4 av1 = *reinterpret_cast<const float4*>(Ap + k0 + 4);
        float4 wv = make_float4(0.f, 0.f, 0.f, 0.f);
        if (gnw < N)
            wv = *reinterpret_cast<const float4*>(Wp + (size_t)k0 * N);

        __syncthreads();
        As[ak + 0][am] = av0.x; As[ak + 1][am] = av0.y;
        As[ak + 2][am] = av0.z; As[ak + 3][am] = av0.w;
        As[ak + 4][am] = av1.x; As[ak + 5][am] = av1.y;
        As[ak + 6][am] = av1.z; As[ak + 7][am] = av1.w;
        *reinterpret_cast<float4*>(&Ws[wk][wn]) = wv;
        __syncthreads();

#pragma unroll
        for (int k = 0; k < 16; k++) {
            float4 a0 = *reinterpret_cast<const float4*>(&As[k][tm]);
            float4 a1 = *reinterpret_cast<const float4*>(&As[k][tm + 4]);
            float4 w  = *reinterpret_cast<const float4*>(&Ws[k][tn]);
            unsigned long long ap[4], wb[4];
            PACK_F32X2(ap[0], a0.x, a0.y);
            PACK_F32X2(ap[1], a0.z, a0.w);
            PACK_F32X2(ap[2], a1.x, a1.y);
            PACK_F32X2(ap[3], a1.z, a1.w);
            PACK_F32X2(wb[0], w.x, w.x);
            PACK_F32X2(wb[1], w.y, w.y);
            PACK_F32X2(wb[2], w.z, w.z);
            PACK_F32X2(wb[3], w.w, w.w);
#pragma unroll
            for (int i = 0; i < 4; i++)
#pragma unroll
                for (int j = 0; j < 4; j++)
                    FMA_F32X2(acc[i][j], ap[i], wb[j], acc[i][j]);
        }
    }

    float* Cb = C + (size_t)blockIdx.z * M * N;
#pragma unroll
    for (int i = 0; i < 4; i++) {
        int r0 = bm + tm + 2 * i;
#pragma unroll
        for (int j = 0; j < 4; j++) {
            int c = bn + tn + j;
            if (c < N) {
                float lo, hi;
                UNPACK_F32X2(lo, hi, acc[i][j]);
                Cb[(size_t)r0 * N + c] = lo;
                Cb[(size_t)(r0 + 1) * N + c] = hi;
            }
        }
    }
}

// ---------------- softmax (attn) ----------------
__global__ void softmax_attn_kernel(const float* __restrict__ attn_b,
                                    float* __restrict__ out) {
    int b = blockIdx.x;
    int t = threadIdx.x;
    float v = attn_b[t];
#pragma unroll
    for (int s = 0; s < 8; s++)
        v += g_part[(size_t)s * B_ * L_ + b * L_ + t];
    __shared__ float red[256];
    red[t] = v;
    __syncthreads();
    for (int s = 128; s; s >>= 1) {
        if (t < s) red[t] = fmaxf(red[t], red[t + s]);
        __syncthreads();
    }
    float m = red[0];
    __syncthreads();
    float e = expf(v - m);
    red[t] = e;
    __syncthreads();
    for (int s = 128; s; s >>= 1) {
        if (t < s) red[t] += red[t + s];
        __syncthreads();
    }
    out[b * L_ + t] = e / red[0];
}

// ---------------- reduce 2 K-partials + bias + relu -> g_x ----------------
__global__ void reduce_relu_kernel(const float* __restrict__ bias) {
    int i = blockIdx.x * blockDim.x + threadIdx.x;
    int j = i & (H_ - 1);
    float v = g_part[i] + g_part[B_ * H_ + i] + bias[j];
    g_x[i] = fmaxf(v, 0.f);
}

// ---------------- attn_applied ----------------
__global__ void attn_apply_kernel(const float* __restrict__ attw,
                                  const float* __restrict__ enc) {
    int b = blockIdx.y;
    int hc = blockIdx.x;
    int t = threadIdx.x;
    __shared__ float w[L_];
    w[t] = attw[b * L_ + t];
    __syncthreads();
    int h = hc * 256 + t;
    const float* e = enc + (size_t)b * L_ * H_ + h;
    float acc = 0.f;
#pragma unroll 8
    for (int l = 0; l < L_; l++)
        acc += w[l] * e[(size_t)l * H_];
    g_attn_applied[(size_t)b * H_ + h] = acc;
}

// ---------------- GRU elementwise ----------------
__global__ void gru_kernel(const float* __restrict__ h,
                           float* __restrict__ new_h) {
    int i = blockIdx.x * blockDim.x + threadIdx.x;
    int b = i >> 10;
    int j = i & (H_ - 1);
    const float* gib = g_gi + (size_t)b * H3_;
    const float* ghb = g_gh + (size_t)b * H3_;
    float r = 1.f / (1.f + expf(-(gib[j] + ghb[j])));
    float z = 1.f / (1.f + expf(-(gib[H_ + j] + ghb[H_ + j])));
    float n = tanhf(gib[2 * H_ + j] + r * ghb[2 * H_ + j]);
    new_h[i] = (1.f - z) * n + z * h[i];
}

// ---------------- log_softmax ----------------
__global__ void logsoftmax_kernel(float* __restrict__ x) {
    int b = blockIdx.x;
    int t = threadIdx.x;
    float* row = x + (size_t)b * V_;
    __shared__ float red[256];
    float m = -1e30f;
    for (int i = t; i < V_; i += 256) m = fmaxf(m, row[i]);
    red[t] = m;
    __syncthreads();
    for (int s = 128; s; s >>= 1) {
        if (t < s) red[t] = fmaxf(red[t], red[t + s]);
        __syncthreads();
    }
    m = red[0];
    __syncthreads();
    float sum = 0.f;
    for (int i = t; i < V_; i += 256) sum += expf(row[i] - m);
    red[t] = sum;
    __syncthreads();
    for (int s = 128; s; s >>= 1) {
        if (t < s) red[t] += red[t + s];
        __syncthreads();
    }
    float lse = m + logf(red[0]);
    for (int i = t; i < V_; i += 256) row[i] -= lse;
}

// ---------------- launch ----------------
extern "C" void kernel_launch(void* const* d_in, const int* in_sizes, int n_in,
                              void* d_out, int out_size) {
    const int*   input_ids = (const int*)d_in[0];
    const float* hidden    = (const float*)d_in[1];
    const float* enc       = (const float*)d_in[2];
    const float* emb       = (const float*)d_in[3];
    const float* attn_w    = (const float*)d_in[4];
    const float* attn_b    = (const float*)d_in[5];
    const float* comb_w    = (const float*)d_in[6];
    const float* comb_b    = (const float*)d_in[7];
    const float* w_ih      = (const float*)d_in[8];
    const float* w_hh      = (const float*)d_in[9];
    const float* b_ih      = (const float*)d_in[10];
    const float* b_hh      = (const float*)d_in[11];
    const float* out_w     = (const float*)d_in[12];
    const float* out_b     = (const float*)d_in[13];

    float* out       = (float*)d_out;
    float* new_h_out = out + (size_t)B_ * V_;
    float* attw_out  = new_h_out + (size_t)B_ * H_;

    float *p_comb, *p_app, *p_x, *p_gi, *p_gh, *p_part;
    cudaGetSymbolAddress((void**)&p_comb, g_comb);
    cudaGetSymbolAddress((void**)&p_app,  g_attn_applied);
    cudaGetSymbolAddress((void**)&p_x,    g_x);
    cudaGetSymbolAddress((void**)&p_gi,   g_gi);
    cudaGetSymbolAddress((void**)&p_gh,   g_gh);
    cudaGetSymbolAddress((void**)&p_part, g_part);

    // opt-in to >48KB dynamic smem for the pipelined GEMMs (idempotent, cheap)
    cudaFuncSetAttribute(gemm_tf32p<0>,
                         cudaFuncAttributeMaxDynamicSharedMemorySize, GSM_BYTES);
    cudaFuncSetAttribute(gemm_tf32p<1>,
                         cudaFuncAttributeMaxDynamicSharedMemorySize, GSM_BYTES);
    cudaFuncSetAttribute(gemm_tf32p<2>,
                         cudaFuncAttributeMaxDynamicSharedMemorySize, GSM_BYTES);

    GemmArgs none = {nullptr, nullptr, nullptr, nullptr};

    // 1. g_comb = [emb[ids] | hidden]
    concat_emb_kernel<<<(B_ * H2_) / 256, 256>>>(input_ids, emb, hidden);
    // 2. attn logits, exact fp32, split-K=8 -> partials
    {
        dim3 g(L_ / 64, B_ / 128, 8);
        gemm_f32x2_split_kernel<<<g, 256>>>(p_comb, attn_w, p_part,
                                            B_, L_, H2_, H2_ / 8);
    }
    // 3. reduce + softmax -> attw_out
    softmax_attn_kernel<<<B_, 256>>>(attn_b, attw_out);
    // 4. attn_applied
    {
        dim3 g(H_ / 256, B_);
        attn_apply_kernel<<<g, 256>>>(attw_out, enc);
    }
    // 5. g_comb = [emb[ids] | attn_applied]
    concat_emb_kernel<<<(B_ * H2_) / 256, 256>>>(input_ids, emb, p_app);
    // 6. comb GEMM (tf32, pipelined), split-K=2 -> partials
    {
        dim3 g(H_ / 64, B_ / 128, 2);
        GemmArgs a0 = {p_comb, comb_w, nullptr, p_part};
        gemm_tf32p<1><<<g, 256, GSM_BYTES>>>(a0, none, B_, H_, H2_, H2_ / 2);
    }
    // 7. x = relu(p0 + p1 + bias)
    reduce_relu_kernel<<<(B_ * H_) / 256, 256>>>(comb_b);
    // 8. gi = x@w_ih+b_ih ; gh = hidden@w_hh+b_hh (dual via grid.z)
    {
        dim3 g(H3_ / 64, B_ / 128, 2);
        GemmArgs a0 = {p_x,    w_ih, b_ih, p_gi};
        GemmArgs a1 = {hidden, w_hh, b_hh, p_gh};
        gemm_tf32p<2><<<g, 256, GSM_BYTES>>>(a0, a1, B_, H3_, H_, H_);
    }
    // 9. GRU -> new_hidden
    gru_kernel<<<(B_ * H_) / 256, 256>>>(hidden, new_h_out);
    // 10. out-proj (tf32, pipelined)
    {
        dim3 g((V_ + 63) / 64, B_ / 128, 1);
        GemmArgs a0 = {new_h_out, out_w, out_b, out};
        gemm_tf32p<0><<<g, 256, GSM_BYTES>>>(a0, none, B_, V_, H_, H_);
    }
    // 11. log_softmax
    logsoftmax_kernel<<<B_, 256>>>(out);
}

// round 11
// speedup vs baseline: 3.6251x; 1.2790x over previous
#include <cuda_runtime.h>
#include <cuda_bf16.h>
#include <cuda_fp16.h>
#include <math.h>
#include <stdint.h>

// Problem dims
#define B_  512
#define H_  1024
#define L_  256
#define V_  10000
#define H2_ 2048
#define H3_ 3072

// ---------------- scratch (device globals; no allocation) ----------------
__device__ float g_comb[B_ * H2_];
__device__ float g_attn_applied[B_ * H_];
__device__ float g_x[B_ * H_];
__device__ float g_gi[B_ * H3_];
__device__ float g_gh[B_ * H3_];
__device__ float g_part[8 * B_ * L_];

// ---------------- helpers ----------------
#define PACK_F32X2(d, lo, hi) \
    asm("mov.b64 %0, {%1, %2};" : "=l"(d) : "f"(lo), "f"(hi))
#define UNPACK_F32X2(lo, hi, v) \
    asm("mov.b64 {%0, %1}, %2;" : "=f"(lo), "=f"(hi) : "l"(v))
#define FMA_F32X2(d, a, b, c) \
    asm("fma.rn.f32x2 %0, %1, %2, %3;" : "=l"(d) : "l"(a), "l"(b), "l"(c))

__device__ __forceinline__ uint32_t packh2(float lo, float hi) {
    __half2 h = __floats2half2_rn(lo, hi);   // .x = lo (low 16 bits)
    return *reinterpret_cast<uint32_t*>(&h);
}

// ---------------- fused gather+concat ----------------
__global__ void concat_emb_kernel(const int* __restrict__ ids,
                                  const float* __restrict__ emb,
                                  const float* __restrict__ other) {
    int i = blockIdx.x * blockDim.x + threadIdx.x;
    int b = i >> 11;
    int j = i & (H2_ - 1);
    g_comb[i] = (j < H_) ? emb[(size_t)ids[b] * H_ + j]
                         : other[(size_t)b * H_ + (j - H_)];
}

// ==================== pipelined fp16 mma GEMM (fp32 accum) ====================
// C = A(M,K) @ W(K,N) (+bias). 256 thr = 8 warps (4m x 2n), BM=128 BN=64 BK=32.
// m16n8k16.f16 fragments; smem holds packed half2 (2 k-elems per u32).
// As [2][128][20] u32 (frag read banks gid*20+tig -> 32 distinct)
// Ws [2][16][72] u32 (k-pair rows; frag read banks tig*8+gid -> 32 distinct)
struct GemmArgs {
    const float* A;
    const float* W;
    const float* bias;
    float* C;
};

template <bool ADDBIAS>
__device__ __forceinline__ void gemm_core(const float* __restrict__ A,
                                          const float* __restrict__ W,
                                          const float* __restrict__ bias,
                                          float* __restrict__ C,
                                          int N, int K, int kbeg, int kT) {
    __shared__ uint32_t As[2][128][20];   // 20480 B
    __shared__ uint32_t Ws[2][16][72];    //  9216 B  (29696 total, static)

    const int tid = threadIdx.x;
    const int lane = tid & 31;
    const int wid = tid >> 5;
    const int gid = lane >> 2;
    const int tig = lane & 3;
    const int warp_m = (wid & 3) * 32;
    const int warp_n = (wid >> 2) * 32;

    const int bm = blockIdx.y * 128;
    const int bn = blockIdx.x * 64;

    // A staging: rows sa_r (+32r), k cols sa_c..sa_c+3 -> 2 u32 pairs
    const int sa_r = tid >> 3;           // 0..31
    const int sa_c = (tid & 7) * 4;      // 0..28
    const int sa_p = sa_c >> 1;          // pair col 0..14
    // W staging: k-pair row pk (covers k=2pk,2pk+1), n cols wc..wc+3
    const int pk = tid >> 4;             // 0..15
    const int wc = (tid & 15) * 4;       // 0..60
    const int gnw = bn + wc;
    const bool wok = (gnw < N);

    const float* Ap = A + (size_t)(bm + sa_r) * K + kbeg + sa_c;
    const float* Wp0 = W + (size_t)(kbeg + 2 * pk) * N + gnw;
    const float* Wp1 = W + (size_t)(kbeg + 2 * pk + 1) * N + gnw;

    float acc[2][4][4];
#pragma unroll
    for (int mi = 0; mi < 2; mi++)
#pragma unroll
        for (int ni = 0; ni < 4; ni++)
#pragma unroll
            for (int r = 0; r < 4; r++) acc[mi][ni][r] = 0.f;

    float4 av[4];
    float4 wv0, wv1;

    auto LDG = [&](int t) {
        const float* ap = Ap + t * 32;
#pragma unroll
        for (int r = 0; r < 4; r++)
            av[r] = *reinterpret_cast<const float4*>(ap + (size_t)(32 * r) * K);
        if (wok) {
            wv0 = *reinterpret_cast<const float4*>(Wp0 + (size_t)(t * 32) * N);
            wv1 = *reinterpret_cast<const float4*>(Wp1 + (size_t)(t * 32) * N);
        } else {
            wv0 = make_float4(0.f, 0.f, 0.f, 0.f);
            wv1 = wv0;
        }
    };

    auto STS = [&](int p) {
#pragma unroll
        for (int r = 0; r < 4; r++) {
            int m = sa_r + 32 * r;
            uint2 t2;
            t2.x = packh2(av[r].x, av[r].y);
            t2.y = packh2(av[r].z, av[r].w);
            *reinterpret_cast<uint2*>(&As[p][m][sa_p]) = t2;
        }
        uint4 t4;
        t4.x = packh2(wv0.x, wv1.x);
        t4.y = packh2(wv0.y, wv1.y);
        t4.z = packh2(wv0.z, wv1.z);
        t4.w = packh2(wv0.w, wv1.w);
        *reinterpret_cast<uint4*>(&Ws[p][pk][wc]) = t4;
    };

    LDG(0);
    STS(0);
    __syncthreads();

    int p = 0;
    for (int t = 0; t < kT; t++) {
        if (t + 1 < kT) LDG(t + 1);

#pragma unroll
        for (int ks = 0; ks < 2; ks++) {       // two k=16 steps per 32-k tile
            const int kp = ks * 8;             // k-pair offset
            uint32_t af[2][4];
#pragma unroll
            for (int mi = 0; mi < 2; mi++) {
                int ar = warp_m + mi * 16 + gid;
                af[mi][0] = As[p][ar][kp + tig];
                af[mi][1] = As[p][ar + 8][kp + tig];
                af[mi][2] = As[p][ar][kp + tig + 4];
                af[mi][3] = As[p][ar + 8][kp + tig + 4];
            }
            uint32_t bf[4][2];
#pragma unroll
            for (int ni = 0; ni < 4; ni++) {
                int bc = warp_n + ni * 8 + gid;
                bf[ni][0] = Ws[p][kp + tig][bc];
                bf[ni][1] = Ws[p][kp + tig + 4][bc];
            }
#pragma unroll
            for (int mi = 0; mi < 2; mi++)
#pragma unroll
                for (int ni = 0; ni < 4; ni++) {
                    asm volatile(
                        "mma.sync.aligned.m16n8k16.row.col.f32.f16.f16.f32 "
                        "{%0,%1,%2,%3}, {%4,%5,%6,%7}, {%8,%9}, {%0,%1,%2,%3};\n"
                        : "+f"(acc[mi][ni][0]), "+f"(acc[mi][ni][1]),
                          "+f"(acc[mi][ni][2]), "+f"(acc[mi][ni][3])
                        : "r"(af[mi][0]), "r"(af[mi][1]),
                          "r"(af[mi][2]), "r"(af[mi][3]),
                          "r"(bf[ni][0]), "r"(bf[ni][1]));
                }
        }

        if (t + 1 < kT) STS(p ^ 1);
        __syncthreads();
        p ^= 1;
    }

    // epilogue
#pragma unroll
    for (int mi = 0; mi < 2; mi++) {
        int r0 = bm + warp_m + mi * 16 + gid;
#pragma unroll
        for (int ni = 0; ni < 4; ni++) {
            int c0 = bn + warp_n + ni * 8 + 2 * tig;
            if (c0 < N) {
                float v0 = acc[mi][ni][0], v1 = acc[mi][ni][1];
                float v2 = acc[mi][ni][2], v3 = acc[mi][ni][3];
                if (ADDBIAS) {
                    float bz0 = bias[c0];
                    float bz1 = (c0 + 1 < N) ? bias[c0 + 1] : 0.f;
                    v0 += bz0; v1 += bz1; v2 += bz0; v3 += bz1;
                }
                C[(size_t)r0 * N + c0] = v0;
                C[(size_t)(r0 + 8) * N + c0] = v2;
                if (c0 + 1 < N) {
                    C[(size_t)r0 * N + c0 + 1] = v1;
                    C[(size_t)(r0 + 8) * N + c0 + 1] = v3;
                }
            }
        }
    }
}

// MODE: 0 = plain (full K, bias), 1 = split-K (z = k-chunk, raw partials),
//       2 = dual (z selects arg set, full K, bias)
template <int MODE>
__global__ void __launch_bounds__(256)
gemm_h16p(GemmArgs g0, GemmArgs g1, int M, int N, int K, int kLen) {
    const GemmArgs ga = (MODE == 2 && blockIdx.z == 1) ? g1 : g0;
    const int kbeg = (MODE == 1) ? blockIdx.z * kLen : 0;
    const int kT = ((MODE == 1) ? kLen : K) / 32;
    float* C = ga.C + ((MODE == 1) ? (size_t)blockIdx.z * M * N : 0);
    if (MODE == 1)
        gemm_core<false>(ga.A, ga.W, ga.bias, C, N, K, kbeg, kT);
    else
        gemm_core<true>(ga.A, ga.W, ga.bias, C, N, K, kbeg, kT);
}

// ---------------- exact-fp32 FFMA2 GEMM (attn logits only) ----------------
__global__ void gemm_f32x2_split_kernel(const float* __restrict__ A,
                                        const float* __restrict__ W,
                                        float* __restrict__ C,
                                        int M, int N, int K, int kLen) {
    __shared__ float As[16][128];
    __shared__ float Ws[16][68];

    const int tid = threadIdx.x;
    const int bm = blockIdx.y * 128;
    const int bn = blockIdx.x * 64;
    const int tm = (tid >> 4) * 8;
    const int tn = (tid & 15) * 4;

    const int am = tid >> 1;
    const int ak = (tid & 1) * 8;
    const float* Ap = A + (size_t)(bm + am) * K + ak;
    const int wk = tid >> 4;
    const int wn = (tid & 15) * 4;
    const int gnw = bn + wn;
    const float* Wp = W + (size_t)wk * N + gnw;

    unsigned long long acc[4][4];
#pragma unroll
    for (int i = 0; i < 4; i++)
#pragma unroll
        for (int j = 0; j < 4; j++) acc[i][j] = 0ULL;

    const int kbeg = blockIdx.z * kLen;
    const int kend = kbeg + kLen;

    for (int k0 = kbeg; k0 < kend; k0 += 16) {
        float4 av0 = *reinterpret_cast<const float4*>(Ap + k0);
        float4 av1 = *reinterpret_cast<const float4*>(Ap + k0 + 4);
        float4 wv = make_float4(0.f, 0.f, 0.f, 0.f);
        if (gnw < N)
            wv = *reinterpret_cast<const float4*>(Wp + (size_t)k0 * N);

        __syncthreads();
        As[ak + 0][am] = av0.x; As[ak + 1][am] = av0.y;
        As[ak + 2][am] = av0.z; As[ak + 3][am] = av0.w;
        As[ak + 4][am] = av1.x; As[ak + 5][am] = av1.y;
        As[ak + 6][am] = av1.z; As[ak + 7][am] = av1.w;
        *reinterpret_cast<float4*>(&Ws[wk][wn]) = wv;
        __syncthreads();

#pragma unroll
        for (int k = 0; k < 16; k++) {
            float4 a0 = *reinterpret_cast<const float4*>(&As[k][tm]);
            float4 a1 = *reinterpret_cast<const float4*>(&As[k][tm + 4]);
            float4 w  = *reinterpret_cast<const float4*>(&Ws[k][tn]);
            unsigned long long ap[4], wb[4];
            PACK_F32X2(ap[0], a0.x, a0.y);
            PACK_F32X2(ap[1], a0.z, a0.w);
            PACK_F32X2(ap[2], a1.x, a1.y);
            PACK_F32X2(ap[3], a1.z, a1.w);
            PACK_F32X2(wb[0], w.x, w.x);
            PACK_F32X2(wb[1], w.y, w.y);
            PACK_F32X2(wb[2], w.z, w.z);
            PACK_F32X2(wb[3], w.w, w.w);
#pragma unroll
            for (int i = 0; i < 4; i++)
#pragma unroll
                for (int j = 0; j < 4; j++)
                    FMA_F32X2(acc[i][j], ap[i], wb[j], acc[i][j]);
        }
    }

    float* Cb = C + (size_t)blockIdx.z * M * N;
#pragma unroll
    for (int i = 0; i < 4; i++) {
        int r0 = bm + tm + 2 * i;
#pragma unroll
        for (int j = 0; j < 4; j++) {
            int c = bn + tn + j;
            if (c < N) {
                float lo, hi;
                UNPACK_F32X2(lo, hi, acc[i][j]);
                Cb[(size_t)r0 * N + c] = lo;
                Cb[(size_t)(r0 + 1) * N + c] = hi;
            }
        }
    }
}

// ---------------- softmax (attn) ----------------
__global__ void softmax_attn_kernel(const float* __restrict__ attn_b,
                                    float* __restrict__ out) {
    int b = blockIdx.x;
    int t = threadIdx.x;
    float v = attn_b[t];
#pragma unroll
    for (int s = 0; s < 8; s++)
        v += g_part[(size_t)s * B_ * L_ + b * L_ + t];
    __shared__ float red[256];
    red[t] = v;
    __syncthreads();
    for (int s = 128; s; s >>= 1) {
        if (t < s) red[t] = fmaxf(red[t], red[t + s]);
        __syncthreads();
    }
    float m = red[0];
    __syncthreads();
    float e = expf(v - m);
    red[t] = e;
    __syncthreads();
    for (int s = 128; s; s >>= 1) {
        if (t < s) red[t] += red[t + s];
        __syncthreads();
    }
    out[b * L_ + t] = e / red[0];
}

// ---------------- reduce 2 K-partials + bias + relu -> g_x ----------------
__global__ void reduce_relu_kernel(const float* __restrict__ bias) {
    int i = blockIdx.x * blockDim.x + threadIdx.x;
    int j = i & (H_ - 1);
    float v = g_part[i] + g_part[B_ * H_ + i] + bias[j];
    g_x[i] = fmaxf(v, 0.f);
}

// ---------------- attn_applied ----------------
__global__ void attn_apply_kernel(const float* __restrict__ attw,
                                  const float* __restrict__ enc) {
    int b = blockIdx.y;
    int hc = blockIdx.x;
    int t = threadIdx.x;
    __shared__ float w[L_];
    w[t] = attw[b * L_ + t];
    __syncthreads();
    int h = hc * 256 + t;
    const float* e = enc + (size_t)b * L_ * H_ + h;
    float acc = 0.f;
#pragma unroll 8
    for (int l = 0; l < L_; l++)
        acc += w[l] * e[(size_t)l * H_];
    g_attn_applied[(size_t)b * H_ + h] = acc;
}

// ---------------- GRU elementwise ----------------
__global__ void gru_kernel(const float* __restrict__ h,
                           float* __restrict__ new_h) {
    int i = blockIdx.x * blockDim.x + threadIdx.x;
    int b = i >> 10;
    int j = i & (H_ - 1);
    const float* gib = g_gi + (size_t)b * H3_;
    const float* ghb = g_gh + (size_t)b * H3_;
    float r = 1.f / (1.f + expf(-(gib[j] + ghb[j])));
    float z = 1.f / (1.f + expf(-(gib[H_ + j] + ghb[H_ + j])));
    float n = tanhf(gib[2 * H_ + j] + r * ghb[2 * H_ + j]);
    new_h[i] = (1.f - z) * n + z * h[i];
}

// ---------------- log_softmax ----------------
__global__ void logsoftmax_kernel(float* __restrict__ x) {
    int b = blockIdx.x;
    int t = threadIdx.x;
    float* row = x + (size_t)b * V_;
    __shared__ float red[256];
    float m = -1e30f;
    for (int i = t; i < V_; i += 256) m = fmaxf(m, row[i]);
    red[t] = m;
    __syncthreads();
    for (int s = 128; s; s >>= 1) {
        if (t < s) red[t] = fmaxf(red[t], red[t + s]);
        __syncthreads();
    }
    m = red[0];
    __syncthreads();
    float sum = 0.f;
    for (int i = t; i < V_; i += 256) sum += expf(row[i] - m);
    red[t] = sum;
    __syncthreads();
    for (int s = 128; s; s >>= 1) {
        if (t < s) red[t] += red[t + s];
        __syncthreads();
    }
    float lse = m + logf(red[0]);
    for (int i = t; i < V_; i += 256) row[i] -= lse;
}

// ---------------- launch ----------------
extern "C" void kernel_launch(void* const* d_in, const int* in_sizes, int n_in,
                              void* d_out, int out_size) {
    const int*   input_ids = (const int*)d_in[0];
    const float* hidden    = (const float*)d_in[1];
    const float* enc       = (const float*)d_in[2];
    const float* emb       = (const float*)d_in[3];
    const float* attn_w    = (const float*)d_in[4];
    const float* attn_b    = (const float*)d_in[5];
    const float* comb_w    = (const float*)d_in[6];
    const float* comb_b    = (const float*)d_in[7];
    const float* w_ih      = (const float*)d_in[8];
    const float* w_hh      = (const float*)d_in[9];
    const float* b_ih      = (const float*)d_in[10];
    const float* b_hh      = (const float*)d_in[11];
    const float* out_w     = (const float*)d_in[12];
    const float* out_b     = (const float*)d_in[13];

    float* out       = (float*)d_out;
    float* new_h_out = out + (size_t)B_ * V_;
    float* attw_out  = new_h_out + (size_t)B_ * H_;

    float *p_comb, *p_app, *p_x, *p_gi, *p_gh, *p_part;
    cudaGetSymbolAddress((void**)&p_comb, g_comb);
    cudaGetSymbolAddress((void**)&p_app,  g_attn_applied);
    cudaGetSymbolAddress((void**)&p_x,    g_x);
    cudaGetSymbolAddress((void**)&p_gi,   g_gi);
    cudaGetSymbolAddress((void**)&p_gh,   g_gh);
    cudaGetSymbolAddress((void**)&p_part, g_part);

    GemmArgs none = {nullptr, nullptr, nullptr, nullptr};

    // 1. g_comb = [emb[ids] | hidden]
    concat_emb_kernel<<<(B_ * H2_) / 256, 256>>>(input_ids, emb, hidden);
    // 2. attn logits, exact fp32, split-K=8 -> partials
    {
        dim3 g(L_ / 64, B_ / 128, 8);
        gemm_f32x2_split_kernel<<<g, 256>>>(p_comb, attn_w, p_part,
                                            B_, L_, H2_, H2_ / 8);
    }
    // 3. reduce + softmax -> attw_out
    softmax_attn_kernel<<<B_, 256>>>(attn_b, attw_out);
    // 4. attn_applied
    {
        dim3 g(H_ / 256, B_);
        attn_apply_kernel<<<g, 256>>>(attw_out, enc);
    }
    // 5. g_comb = [emb[ids] | attn_applied]
    concat_emb_kernel<<<(B_ * H2_) / 256, 256>>>(input_ids, emb, p_app);
    // 6. comb GEMM (fp16 mma), split-K=2 -> partials
    {
        dim3 g(H_ / 64, B_ / 128, 2);
        GemmArgs a0 = {p_comb, comb_w, nullptr, p_part};
        gemm_h16p<1><<<g, 256>>>(a0, none, B_, H_, H2_, H2_ / 2);
    }
    // 7. x = relu(p0 + p1 + bias)
    reduce_relu_kernel<<<(B_ * H_) / 256, 256>>>(comb_b);
    // 8. gi = x@w_ih+b_ih ; gh = hidden@w_hh+b_hh (dual via grid.z)
    {
        dim3 g(H3_ / 64, B_ / 128, 2);
        GemmArgs a0 = {p_x,    w_ih, b_ih, p_gi};
        GemmArgs a1 = {hidden, w_hh, b_hh, p_gh};
        gemm_h16p<2><<<g, 256>>>(a0, a1, B_, H3_, H_, H_);
    }
    // 9. GRU -> new_hidden
    gru_kernel<<<(B_ * H_) / 256, 256>>>(hidden, new_h_out);
    // 10. out-proj (fp16 mma)
    {
        dim3 g((V_ + 63) / 64, B_ / 128, 1);
        GemmArgs a0 = {new_h_out, out_w, out_b, out};
        gemm_h16p<0><<<g, 256>>>(a0, none, B_, V_, H_, H_);
    }
    // 11. log_softmax
    logsoftmax_kernel<<<B_, 256>>>(out);
}